// round 17
// baseline (speedup 1.0000x reference)
#include <cuda_runtime.h>
#include <cuda_bf16.h>

#define BSZ 4
#define NF  512
#define C8  64
#define HW  4096

// Scratch (device globals; no allocation allowed in kernel_launch)
__device__ __nv_bfloat16 g_q_hi[(size_t)BSZ * C8 * HW];       // 2MB each
__device__ __nv_bfloat16 g_q_lo[(size_t)BSZ * C8 * HW];
__device__ __nv_bfloat16 g_k_hi[(size_t)BSZ * C8 * HW];
__device__ __nv_bfloat16 g_k_lo[(size_t)BSZ * C8 * HW];
__device__ __nv_bfloat16 g_vbf [(size_t)BSZ * NF * HW];       // v bf16, 16.8MB
__device__ __nv_bfloat16 g_attn_bf[(size_t)BSZ * HW * HW];    // UNNORMALIZED exp(scores), bf16, 134MB
__device__ float         g_rowsum[(size_t)BSZ * HW];          // per-row exp sums, 64KB

// ---------------------------------------------------------------------------
// Helpers
// ---------------------------------------------------------------------------
__device__ __forceinline__ unsigned f2tf32(float f) {
    unsigned u;
    asm("cvt.rna.tf32.f32 %0, %1;" : "=r"(u) : "f"(f));
    return u;
}
__device__ __forceinline__ void split_tf32(float v, unsigned& hi, unsigned& lo) {
    hi = f2tf32(v);
    lo = f2tf32(v - __uint_as_float(hi));
}
__device__ __forceinline__ unsigned pack_bf16x2(float lo, float hi) {
    unsigned r;
    asm("cvt.rn.bf16x2.f32 %0, %1, %2;" : "=r"(r) : "f"(hi), "f"(lo));
    return r;
}
__device__ __forceinline__ void split2(float a0, float a1, unsigned& h, unsigned& l) {
    h = pack_bf16x2(a0, a1);
    float r0 = a0 - __uint_as_float(h << 16);
    float r1 = a1 - __uint_as_float(h & 0xffff0000u);
    l = pack_bf16x2(r0, r1);
}

__device__ __forceinline__ void mma16n8k8(float* c, const unsigned* a, const unsigned* b) {
    asm volatile(
        "mma.sync.aligned.m16n8k8.row.col.f32.tf32.tf32.f32 "
        "{%0,%1,%2,%3}, {%4,%5,%6,%7}, {%8,%9}, {%0,%1,%2,%3};\n"
        : "+f"(c[0]), "+f"(c[1]), "+f"(c[2]), "+f"(c[3])
        : "r"(a[0]), "r"(a[1]), "r"(a[2]), "r"(a[3]), "r"(b[0]), "r"(b[1]));
}
__device__ __forceinline__ void mma16n8k16bf(float* c, const unsigned* a, const unsigned* b) {
    asm volatile(
        "mma.sync.aligned.m16n8k16.row.col.f32.bf16.bf16.f32 "
        "{%0,%1,%2,%3}, {%4,%5,%6,%7}, {%8,%9}, {%0,%1,%2,%3};\n"
        : "+f"(c[0]), "+f"(c[1]), "+f"(c[2]), "+f"(c[3])
        : "r"(a[0]), "r"(a[1]), "r"(a[2]), "r"(a[3]), "r"(b[0]), "r"(b[1]));
}
__device__ __forceinline__ void ldsm_x4_t(unsigned* r, unsigned addr) {
    asm volatile("ldmatrix.sync.aligned.m8n8.x4.trans.shared.b16 {%0,%1,%2,%3}, [%4];"
                 : "=r"(r[0]), "=r"(r[1]), "=r"(r[2]), "=r"(r[3]) : "r"(addr));
}
__device__ __forceinline__ void ldsm_x2_t(unsigned* r, unsigned addr) {
    asm volatile("ldmatrix.sync.aligned.m8n8.x2.trans.shared.b16 {%0,%1}, [%2];"
                 : "=r"(r[0]), "=r"(r[1]) : "r"(addr));
}
__device__ __forceinline__ void ldsm_x4(unsigned* r, unsigned addr) {
    asm volatile("ldmatrix.sync.aligned.m8n8.x4.shared.b16 {%0,%1,%2,%3}, [%4];"
                 : "=r"(r[0]), "=r"(r[1]), "=r"(r[2]), "=r"(r[3]) : "r"(addr));
}
__device__ __forceinline__ void ldsm_x2(unsigned* r, unsigned addr) {
    asm volatile("ldmatrix.sync.aligned.m8n8.x2.shared.b16 {%0,%1}, [%2];"
                 : "=r"(r[0]), "=r"(r[1]) : "r"(addr));
}

#define CP_ASYNC16(smem_u32, gptr) \
    asm volatile("cp.async.cg.shared.global [%0], [%1], 16;\n" :: "r"(smem_u32), "l"(gptr))
#define CP_COMMIT() asm volatile("cp.async.commit_group;\n" ::: "memory")
#define CP_WAIT0()  asm volatile("cp.async.wait_group 0;\n" ::: "memory")

// XOR swizzle for transposed fp32 [k][128] tiles
#define SWZ(k, col) ((col) ^ (((k) & 3) << 3))

__device__ __forceinline__ const float* w_row_ptr(int o, const float* Wq,
                                                  const float* Wk, const float* Wv) {
    if (o < C8)      return Wq + (size_t)o * NF;
    if (o < 2 * C8)  return Wk + (size_t)(o - C8) * NF;
    return Wv + (size_t)(o - 2 * C8) * NF;
}
__device__ __forceinline__ float bias_val(int o, const float* bq,
                                          const float* bk, const float* bv) {
    if (o < C8)      return bq[o];
    if (o < 2 * C8)  return bk[o - C8];
    return bv[o - 2 * C8];
}

// ---------------------------------------------------------------------------
// Kernel 0: zero the row-sum accumulator (graph-safe, deterministic)
// ---------------------------------------------------------------------------
__global__ void zero_rowsum()
{
    g_rowsum[blockIdx.x * 1024 + threadIdx.x] = 0.0f;
}

// ---------------------------------------------------------------------------
// Kernel 1: QKV projection (unchanged)
// ---------------------------------------------------------------------------
template<bool HP>
__global__ __launch_bounds__(256) void qkv_mma(
    const float* __restrict__ x,
    const float* __restrict__ Wq, const float* __restrict__ bq,
    const float* __restrict__ Wk, const float* __restrict__ bk,
    const float* __restrict__ Wv, const float* __restrict__ bv,
    int m_base)
{
    __shared__ float As[2][128][20];
    __shared__ float Bs[2][16][128];

    const int b     = blockIdx.z;
    const int m_blk = m_base + blockIdx.y * 128;
    const int n_blk = blockIdx.x * 128;
    const float* xb = x + (size_t)b * NF * HW;

    const int tid  = threadIdx.x;
    const int warp = tid >> 5, lane = tid & 31;
    const int g    = lane >> 2, tig = lane & 3;
    const int wm   = (warp >> 2) * 64, wn = (warp & 3) * 32;

    const unsigned as0 = (unsigned)__cvta_generic_to_shared(&As[0][0][0]);
    const unsigned bs0 = (unsigned)__cvta_generic_to_shared(&Bs[0][0][0]);

    float acc[4][4][4] = {};
    const int T = NF / 16;

    {
        const int k0 = 0;
        int c = tid, row = c >> 2, off = (c & 3) * 4;
        CP_ASYNC16(as0 + row * 80 + off * 4, w_row_ptr(m_blk + row, Wq, Wk, Wv) + k0 + off);
        c = tid + 256; row = c >> 2; off = (c & 3) * 4;
        CP_ASYNC16(as0 + row * 80 + off * 4, w_row_ptr(m_blk + row, Wq, Wk, Wv) + k0 + off);
        c = tid;       { int r = c >> 5, o2 = (c & 31) * 4, sw = SWZ(r, o2);
            CP_ASYNC16(bs0 + r * 512 + sw * 4, xb + (size_t)(k0 + r) * HW + n_blk + o2); }
        c = tid + 256; { int r = c >> 5, o2 = (c & 31) * 4, sw = SWZ(r, o2);
            CP_ASYNC16(bs0 + r * 512 + sw * 4, xb + (size_t)(k0 + r) * HW + n_blk + o2); }
        CP_COMMIT();
    }

    for (int t = 0; t < T; ++t) {
        CP_WAIT0();
        __syncthreads();
        if (t + 1 < T) {
            const int s = (t + 1) & 1;
            const int k0 = (t + 1) * 16;
            int c = tid, row = c >> 2, off = (c & 3) * 4;
            CP_ASYNC16(as0 + s * 10240 + row * 80 + off * 4,
                       w_row_ptr(m_blk + row, Wq, Wk, Wv) + k0 + off);
            c = tid + 256; row = c >> 2; off = (c & 3) * 4;
            CP_ASYNC16(as0 + s * 10240 + row * 80 + off * 4,
                       w_row_ptr(m_blk + row, Wq, Wk, Wv) + k0 + off);
            c = tid;       { int r = c >> 5, o2 = (c & 31) * 4, sw = SWZ(r, o2);
                CP_ASYNC16(bs0 + s * 8192 + r * 512 + sw * 4,
                           xb + (size_t)(k0 + r) * HW + n_blk + o2); }
            c = tid + 256; { int r = c >> 5, o2 = (c & 31) * 4, sw = SWZ(r, o2);
                CP_ASYNC16(bs0 + s * 8192 + r * 512 + sw * 4,
                           xb + (size_t)(k0 + r) * HW + n_blk + o2); }
            CP_COMMIT();
        }
        const int s = t & 1;
        #pragma unroll
        for (int ks = 0; ks < 16; ks += 8) {
            unsigned af[4][4], bf[4][2];
            unsigned afl[4][4], bfl[4][2];
            #pragma unroll
            for (int mi = 0; mi < 4; ++mi) {
                const int row = wm + mi * 16 + g;
                float a0 = As[s][row][ks + tig];
                float a1 = As[s][row + 8][ks + tig];
                float a2 = As[s][row][ks + tig + 4];
                float a3 = As[s][row + 8][ks + tig + 4];
                if (HP) {
                    split_tf32(a0, af[mi][0], afl[mi][0]);
                    split_tf32(a1, af[mi][1], afl[mi][1]);
                    split_tf32(a2, af[mi][2], afl[mi][2]);
                    split_tf32(a3, af[mi][3], afl[mi][3]);
                } else {
                    af[mi][0] = f2tf32(a0); af[mi][1] = f2tf32(a1);
                    af[mi][2] = f2tf32(a2); af[mi][3] = f2tf32(a3);
                }
            }
            #pragma unroll
            for (int ni = 0; ni < 4; ++ni) {
                const int n = wn + ni * 8 + g;
                const int k0q = ks + tig, k1q = ks + tig + 4;
                float b0 = Bs[s][k0q][SWZ(k0q, n)];
                float b1 = Bs[s][k1q][SWZ(k1q, n)];
                if (HP) {
                    split_tf32(b0, bf[ni][0], bfl[ni][0]);
                    split_tf32(b1, bf[ni][1], bfl[ni][1]);
                } else {
                    bf[ni][0] = f2tf32(b0); bf[ni][1] = f2tf32(b1);
                }
            }
            #pragma unroll
            for (int mi = 0; mi < 4; ++mi)
                #pragma unroll
                for (int ni = 0; ni < 4; ++ni) {
                    mma16n8k8(acc[mi][ni], af[mi], bf[ni]);
                    if (HP) {
                        mma16n8k8(acc[mi][ni], afl[mi], bf[ni]);
                        mma16n8k8(acc[mi][ni], af[mi], bfl[ni]);
                    }
                }
        }
    }

    #pragma unroll
    for (int mi = 0; mi < 4; ++mi) {
        #pragma unroll
        for (int ni = 0; ni < 4; ++ni) {
            const int m = m_blk + wm + mi * 16 + g;
            const int n = n_blk + wn + ni * 8 + tig * 2;
            const float bias0 = bias_val(m, bq, bk, bv);
            const float bias1 = bias_val(m + 8, bq, bk, bv);
            float v00 = acc[mi][ni][0] + bias0, v01 = acc[mi][ni][1] + bias0;
            float v10 = acc[mi][ni][2] + bias1, v11 = acc[mi][ni][3] + bias1;
            if (HP) {
                unsigned h, l;
                {
                    __nv_bfloat16* hp_ = (m < C8) ? g_q_hi : g_k_hi;
                    __nv_bfloat16* lp_ = (m < C8) ? g_q_lo : g_k_lo;
                    const size_t idx = ((size_t)b * C8 + (m & 63)) * HW + n;
                    split2(v00, v01, h, l);
                    *(unsigned*)(hp_ + idx) = h;
                    *(unsigned*)(lp_ + idx) = l;
                }
                {
                    const int m2 = m + 8;
                    __nv_bfloat16* hp_ = (m2 < C8) ? g_q_hi : g_k_hi;
                    __nv_bfloat16* lp_ = (m2 < C8) ? g_q_lo : g_k_lo;
                    const size_t idx = ((size_t)b * C8 + (m2 & 63)) * HW + n;
                    split2(v10, v11, h, l);
                    *(unsigned*)(hp_ + idx) = h;
                    *(unsigned*)(lp_ + idx) = l;
                }
            } else {
                __nv_bfloat16* outp = g_vbf + (size_t)b * NF * HW;
                const int vm = m - 2 * C8;
                *(unsigned*)(outp + (size_t)vm * HW + n)       = pack_bf16x2(v00, v01);
                *(unsigned*)(outp + (size_t)(vm + 8) * HW + n) = pack_bf16x2(v10, v11);
            }
        }
    }
}

// ---------------------------------------------------------------------------
// Kernel 2 (RESTRUCTURED): persistent scores. Each CTA: K-tile resident,
// loops 16 Q-tiles with double-buffered prefetch. Epilogue per tile:
// e = exp(score) -> bf16 + rowsum atomics (unchanged math).
// ---------------------------------------------------------------------------
#define SPAD 136
#define STILE (C8 * SPAD)               // elements per smem array
#define SC_NT 16                        // Q-tiles per CTA (grid.x = 2 groups)
#define SC_SMEM (6 * STILE * 2)         // K(h,l) + 2 stages of Q(h,l), bytes

__global__ __launch_bounds__(256) void scores_mma()
{
    extern __shared__ __nv_bfloat16 smx[];
    // layout: Kh | Kl | Qh0 | Ql0 | Qh1 | Ql1
    const unsigned skh = (unsigned)__cvta_generic_to_shared(smx);
    const unsigned skl = skh + STILE * 2;
    const unsigned sq0 = skl + STILE * 2;     // Qh0 (Ql0 = +STILE*2)
    const unsigned sq1 = sq0 + 2 * STILE * 2; // Qh1 (Ql1 = +STILE*2)

    const int b     = blockIdx.z;
    const int m_blk = blockIdx.y * 128;   // i (softmax rows)
    const int ng    = blockIdx.x;         // 0..1 column parity
    __nv_bfloat16* cp = g_attn_bf + (size_t)b * HW * HW;
    float* rs = g_rowsum + (size_t)b * HW;

    const int tid  = threadIdx.x;
    const int warp = tid >> 5, lane = tid & 31;
    const int g    = lane >> 2, tig = lane & 3;
    const int wm   = (warp >> 2) * 64, wn = (warp & 3) * 32;

    // chunk assignment for a 64x128 bf16 tile: 1024 chunks of 16B per array
    const int l_row = tid >> 1;               // unused pattern placeholder
    (void)l_row;

    // initial: load K (both arrays) + Q tile 0
    #pragma unroll
    for (int z = 0; z < 4; ++z) {
        const int cidx = z * 256 + tid;
        const int row  = cidx >> 4;
        const int off  = (cidx & 15) * 8;
        const unsigned so = (unsigned)(row * SPAD + off) * 2;
        const size_t gk = ((size_t)b * C8 + row) * HW + m_blk + off;
        CP_ASYNC16(skh + so, g_k_hi + gk);
        CP_ASYNC16(skl + so, g_k_lo + gk);
        const size_t gq = ((size_t)b * C8 + row) * HW + (size_t)ng * 128 + off;
        CP_ASYNC16(sq0 + so, g_q_hi + gq);
        CP_ASYNC16(sq0 + STILE * 2 + so, g_q_lo + gq);
    }
    CP_COMMIT();

    const int a_krow = (lane & 7) + ((lane >> 4) << 3);
    const int a_coff = ((lane >> 3) & 1) << 3;
    const int b_krow = (lane & 15);

    #pragma unroll 1
    for (int tt = 0; tt < SC_NT; ++tt) {
        CP_WAIT0();
        __syncthreads();
        if (tt + 1 < SC_NT) {
            const unsigned sq = ((tt + 1) & 1) ? sq1 : sq0;
            const int n0 = ((tt + 1) * 2 + ng) * 128;
            #pragma unroll
            for (int z = 0; z < 4; ++z) {
                const int cidx = z * 256 + tid;
                const int row  = cidx >> 4;
                const int off  = (cidx & 15) * 8;
                const unsigned so = (unsigned)(row * SPAD + off) * 2;
                const size_t gq = ((size_t)b * C8 + row) * HW + n0 + off;
                CP_ASYNC16(sq + so, g_q_hi + gq);
                CP_ASYNC16(sq + STILE * 2 + so, g_q_lo + gq);
            }
            CP_COMMIT();
        }
        const unsigned sqh = (tt & 1) ? sq1 : sq0;
        const unsigned sql = sqh + STILE * 2;
        const int n_blk = (tt * 2 + ng) * 128;

        float acc[4][4][4] = {};

        #pragma unroll
        for (int kc = 0; kc < 4; ++kc) {
            const int c0 = kc * 16;
            unsigned ah[4][4], al[4][4], bh[4][2], bl[4][2];
            #pragma unroll
            for (int mi = 0; mi < 4; ++mi) {
                const int col = wm + mi * 16 + a_coff;
                const unsigned off = (unsigned)((c0 + a_krow) * SPAD + col) * 2;
                ldsm_x4_t(ah[mi], skh + off);
                ldsm_x4_t(al[mi], skl + off);
            }
            #pragma unroll
            for (int ni = 0; ni < 4; ++ni) {
                const int col = wn + ni * 8;
                const unsigned off = (unsigned)((c0 + b_krow) * SPAD + col) * 2;
                ldsm_x2_t(bh[ni], sqh + off);
                ldsm_x2_t(bl[ni], sql + off);
            }
            #pragma unroll
            for (int mi = 0; mi < 4; ++mi)
                #pragma unroll
                for (int ni = 0; ni < 4; ++ni) {
                    mma16n8k16bf(acc[mi][ni], ah[mi], bh[ni]);
                    mma16n8k16bf(acc[mi][ni], ah[mi], bl[ni]);
                    mma16n8k16bf(acc[mi][ni], al[mi], bh[ni]);
                }
        }

        // Epilogue: e = exp(score); bf16 store; per-row sums -> atomics
        #pragma unroll
        for (int mi = 0; mi < 4; ++mi) {
            const int m = m_blk + wm + mi * 16 + g;
            float s0 = 0.0f, s1 = 0.0f;
            #pragma unroll
            for (int ni = 0; ni < 4; ++ni) {
                const int n = n_blk + wn + ni * 8 + tig * 2;
                float e00 = __expf(acc[mi][ni][0]);
                float e01 = __expf(acc[mi][ni][1]);
                float e10 = __expf(acc[mi][ni][2]);
                float e11 = __expf(acc[mi][ni][3]);
                *(unsigned*)(cp + (size_t)m * HW + n)       = pack_bf16x2(e00, e01);
                *(unsigned*)(cp + (size_t)(m + 8) * HW + n) = pack_bf16x2(e10, e11);
                s0 += e00 + e01;
                s1 += e10 + e11;
            }
            s0 += __shfl_xor_sync(0xffffffffu, s0, 1);
            s0 += __shfl_xor_sync(0xffffffffu, s0, 2);
            s1 += __shfl_xor_sync(0xffffffffu, s1, 1);
            s1 += __shfl_xor_sync(0xffffffffu, s1, 2);
            if (tig == 0) {
                atomicAdd(rs + m, s0);
                atomicAdd(rs + m + 8, s1);
            }
        }
    }
}

// ---------------------------------------------------------------------------
// Kernel 3: out GEMM (unchanged from 455us build)
// ---------------------------------------------------------------------------
#define OPAD 72
#define OSTG (128 * OPAD)
#define OUT_SMEM (4 * OSTG * 2)

__global__ __launch_bounds__(256, 2) void out_mma_bf(
    const float* __restrict__ x,
    const float* __restrict__ alphap,
    float* __restrict__ out)
{
    extern __shared__ __nv_bfloat16 smo[];
    const unsigned as0 = (unsigned)__cvta_generic_to_shared(smo);
    const unsigned bs0 = as0 + 2 * OSTG * 2;

    const int b     = blockIdx.z;
    const int m_blk = blockIdx.y * 128;   // c
    const int n_blk = blockIdx.x * 128;   // i
    const __nv_bfloat16* vp = g_vbf + (size_t)b * NF * HW;
    const __nv_bfloat16* ap = g_attn_bf + (size_t)b * HW * HW;
    const float* xb = x + (size_t)b * NF * HW;
    float* ob = out + (size_t)b * NF * HW;
    const float* rs = g_rowsum + (size_t)b * HW;

    const int tid  = threadIdx.x;
    const int warp = tid >> 5, lane = tid & 31;
    const int g    = lane >> 2, tig = lane & 3;
    const int wm   = (warp >> 2) * 64, wn = (warp & 3) * 32;

    const int a_r = lane & 15;
    const int a_c = (lane >> 4) << 3;
    const int b_r = lane & 7;
    const int b_c = ((lane >> 3) & 1) << 3;

    float acc[4][4][4] = {};
    const int T = HW / 64;

    {
        #pragma unroll
        for (int h = 0; h < 4; ++h) {
            const int c = tid + h * 256;
            const int row = c >> 3, off = (c & 7) * 8;
            const unsigned so = (unsigned)(row * OPAD + off) * 2;
            CP_ASYNC16(as0 + so, vp + (size_t)(m_blk + row) * HW + off);
            CP_ASYNC16(bs0 + so, ap + (size_t)(n_blk + row) * HW + off);
        }
        CP_COMMIT();
    }

    for (int t = 0; t < T; ++t) {
        CP_WAIT0();
        __syncthreads();
        if (t + 1 < T) {
            const unsigned sb = ((t + 1) & 1) * (unsigned)(OSTG * 2);
            const int k0 = (t + 1) * 64;
            #pragma unroll
            for (int h = 0; h < 4; ++h) {
                const int c = tid + h * 256;
                const int row = c >> 3, off = (c & 7) * 8;
                const unsigned so = sb + (unsigned)(row * OPAD + off) * 2;
                CP_ASYNC16(as0 + so, vp + (size_t)(m_blk + row) * HW + k0 + off);
                CP_ASYNC16(bs0 + so, ap + (size_t)(n_blk + row) * HW + k0 + off);
            }
            CP_COMMIT();
        }
        const unsigned sb = (t & 1) * (unsigned)(OSTG * 2);
        #pragma unroll
        for (int ks = 0; ks < 64; ks += 16) {
            unsigned af[4][4], bf[4][2];
            #pragma unroll
            for (int mi = 0; mi < 4; ++mi) {
                const unsigned addr = as0 + sb +
                    (unsigned)((wm + mi * 16 + a_r) * OPAD + ks + a_c) * 2;
                ldsm_x4(af[mi], addr);
            }
            #pragma unroll
            for (int ni = 0; ni < 4; ++ni) {
                const unsigned addr = bs0 + sb +
                    (unsigned)((wn + ni * 8 + b_r) * OPAD + ks + b_c) * 2;
                ldsm_x2(bf[ni], addr);
            }
            #pragma unroll
            for (int mi = 0; mi < 4; ++mi)
                #pragma unroll
                for (int ni = 0; ni < 4; ++ni)
                    mma16n8k16bf(acc[mi][ni], af[mi], bf[ni]);
        }
    }

    const float alpha = alphap[0];
    #pragma unroll
    for (int ni = 0; ni < 4; ++ni) {
        const int n = n_blk + wn + ni * 8 + tig * 2;
        const float inv0 = alpha / rs[n];
        const float inv1 = alpha / rs[n + 1];
        #pragma unroll
        for (int mi = 0; mi < 4; ++mi) {
            const int m = m_blk + wm + mi * 16 + g;
            const size_t i0 = (size_t)m * HW + n;
            const size_t i1 = (size_t)(m + 8) * HW + n;
            float2 x0 = *(const float2*)(xb + i0);
            float2 x1 = *(const float2*)(xb + i1);
            float2 r0 = { x0.x + inv0 * acc[mi][ni][0], x0.y + inv1 * acc[mi][ni][1] };
            float2 r1 = { x1.x + inv0 * acc[mi][ni][2], x1.y + inv1 * acc[mi][ni][3] };
            *(float2*)(ob + i0) = r0;
            *(float2*)(ob + i1) = r1;
        }
    }
}

// ---------------------------------------------------------------------------
extern "C" void kernel_launch(void* const* d_in, const int* in_sizes, int n_in,
                              void* d_out, int out_size)
{
    const float* x     = (const float*)d_in[0];
    const float* Wq    = (const float*)d_in[1];
    const float* bq    = (const float*)d_in[2];
    const float* Wk    = (const float*)d_in[3];
    const float* bk    = (const float*)d_in[4];
    const float* Wv    = (const float*)d_in[5];
    const float* bv    = (const float*)d_in[6];
    const float* alpha = (const float*)d_in[7];
    float* out = (float*)d_out;

    cudaFuncSetAttribute(scores_mma, cudaFuncAttributeMaxDynamicSharedMemorySize,
                         SC_SMEM);
    cudaFuncSetAttribute(out_mma_bf, cudaFuncAttributeMaxDynamicSharedMemorySize,
                         OUT_SMEM);

    zero_rowsum<<<BSZ * HW / 1024, 1024>>>();
    qkv_mma<true><<<dim3(HW / 128, 1, BSZ), 256>>>(x, Wq, bq, Wk, bk, Wv, bv, 0);
    qkv_mma<false><<<dim3(HW / 128, 4, BSZ), 256>>>(x, Wq, bq, Wk, bk, Wv, bv, 128);
    scores_mma<<<dim3(2, HW / 128, BSZ), 256, SC_SMEM>>>();
    out_mma_bf<<<dim3(HW / 128, NF / 128, BSZ), 256, OUT_SMEM>>>(x, alpha, out);
}